// round 1
// baseline (speedup 1.0000x reference)
#include <cuda_runtime.h>
#include <cstdint>

#define NTOK 6272
#define CDIM 1024
#define HEADS 16
#define HD 64
#define SFR 32
#define PTOK 196
#define MKV 1960
#define CH 28   // key chunk (1960 = 70*28)

// Scratch (no allocations allowed anywhere)
__device__ float g_qkv[3u * HEADS * NTOK * HD];   // [part][h][n][d]
__device__ float g_att[(size_t)NTOK * CDIM];      // attention out, token-major

// ---------------------------------------------------------------------------
// SGEMM: 128x128 tile, K-tile 8, 256 threads, 8x8 per thread.
// MODE 0: C = x @ W_qkv + b, scatter epilogue into g_qkv [part][h][n][d]
// MODE 1: C = g_att @ W_proj + b, plain row-major output
// ---------------------------------------------------------------------------
template <int MODE>
__global__ void __launch_bounds__(256, 2)
sgemm_kernel(const float* __restrict__ Aparam, const float* __restrict__ B,
             const float* __restrict__ bias, float* __restrict__ C, int Nc)
{
    const int K = 1024;
    const float* A = (MODE == 0) ? Aparam : (const float*)g_att;

    __shared__ float As[8][128];
    __shared__ float Bs[8][128];

    const int tid = threadIdx.x;
    const int bm = blockIdx.y * 128, bn = blockIdx.x * 128;
    const int arow = tid >> 1, acol = (tid & 1) << 2;
    const int brow = tid >> 5, bcol = (tid & 31) << 2;
    const int tx = tid & 15, ty = tid >> 4;

    const float* Aptr = A + (size_t)(bm + arow) * K + acol;
    const float* Bptr = B + (size_t)brow * Nc + bn + bcol;

    float acc[8][8];
#pragma unroll
    for (int i = 0; i < 8; i++)
#pragma unroll
        for (int j = 0; j < 8; j++) acc[i][j] = 0.f;

    float4 pa = *(const float4*)Aptr;
    float4 pb = *(const float4*)Bptr;

    for (int k0 = 0; k0 < K; k0 += 8) {
        As[acol + 0][arow] = pa.x;
        As[acol + 1][arow] = pa.y;
        As[acol + 2][arow] = pa.z;
        As[acol + 3][arow] = pa.w;
        *(float4*)&Bs[brow][bcol] = pb;
        __syncthreads();

        if (k0 + 8 < K) {
            pa = *(const float4*)(Aptr + k0 + 8);
            pb = *(const float4*)(Bptr + (size_t)(k0 + 8) * Nc);
        }

#pragma unroll
        for (int kk = 0; kk < 8; kk++) {
            float4 a0 = *(float4*)&As[kk][ty * 4];
            float4 a1 = *(float4*)&As[kk][64 + ty * 4];
            float4 b0 = *(float4*)&Bs[kk][tx * 4];
            float4 b1 = *(float4*)&Bs[kk][64 + tx * 4];
            float av[8] = {a0.x, a0.y, a0.z, a0.w, a1.x, a1.y, a1.z, a1.w};
            float bv[8] = {b0.x, b0.y, b0.z, b0.w, b1.x, b1.y, b1.z, b1.w};
#pragma unroll
            for (int i = 0; i < 8; i++)
#pragma unroll
                for (int j = 0; j < 8; j++) acc[i][j] += av[i] * bv[j];
        }
        __syncthreads();
    }

#pragma unroll
    for (int i = 0; i < 8; i++) {
        int m = bm + ((i < 4) ? (ty * 4 + i) : (64 + ty * 4 + (i - 4)));
#pragma unroll
        for (int j = 0; j < 8; j++) {
            int col = bn + ((j < 4) ? (tx * 4 + j) : (64 + tx * 4 + (j - 4)));
            float val = acc[i][j] + bias[col];
            if (MODE == 0) {
                int part = col >> 10;
                int hd = col & 1023;
                int h = hd >> 6;
                int d = hd & 63;
                g_qkv[(((size_t)part * HEADS + h) * NTOK + m) * HD + d] = val;
            } else {
                C[(size_t)m * Nc + col] = val;
            }
        }
    }
}

// ---------------------------------------------------------------------------
// LayerNorm over D=64 on q (part 0) and k (part 1). One warp per vector.
// ---------------------------------------------------------------------------
__global__ void __launch_bounds__(256)
ln_kernel(const float* __restrict__ qg, const float* __restrict__ qb,
          const float* __restrict__ kg, const float* __restrict__ kb)
{
    const int NV = 2 * HEADS * NTOK;
    int warp = (blockIdx.x * blockDim.x + threadIdx.x) >> 5;
    int lane = threadIdx.x & 31;
    if (warp >= NV) return;

    float* v = g_qkv + (size_t)warp * HD;
    float2 x = *(float2*)&v[lane * 2];

    float s = x.x + x.y;
#pragma unroll
    for (int o = 16; o; o >>= 1) s += __shfl_xor_sync(0xffffffffu, s, o);
    float mu = s * (1.f / 64.f);

    float dx = x.x - mu, dy = x.y - mu;
    float ss = dx * dx + dy * dy;
#pragma unroll
    for (int o = 16; o; o >>= 1) ss += __shfl_xor_sync(0xffffffffu, ss, o);
    float rstd = rsqrtf(ss * (1.f / 64.f) + 1e-6f);

    bool isq = warp < HEADS * NTOK;
    const float* g = isq ? qg : kg;
    const float* b = isq ? qb : kb;
    x.x = dx * rstd * g[lane * 2] + b[lane * 2];
    x.y = dy * rstd * g[lane * 2 + 1] + b[lane * 2 + 1];
    *(float2*)&v[lane * 2] = x;
}

// ---------------------------------------------------------------------------
// Sparse attention: one block per (frame s, head h). Thread t = query row.
// Online softmax over MKV=1960 gathered keys in chunks of CH=28.
// ---------------------------------------------------------------------------
__global__ void __launch_bounds__(224)
attn_kernel(const int* __restrict__ gidx, const float* __restrict__ abias)
{
    const int s = blockIdx.x;
    const int h = blockIdx.y;
    const float* qbuf = g_qkv + (size_t)h * NTOK * HD;
    const float* kbuf = g_qkv + (size_t)(HEADS + h) * NTOK * HD;
    const float* vbuf = g_qkv + (size_t)(2 * HEADS + h) * NTOK * HD;

    __shared__ float Ks[CH][HD];
    __shared__ float Vs[CH][HD];
    __shared__ float bias_s[CH];

    const int tid = threadIdx.x;
    const int p = tid;

    float4 qv[16];
    if (p < PTOK) {
        const float4* qp = (const float4*)(qbuf + (size_t)(s * PTOK + p) * HD);
#pragma unroll
        for (int i = 0; i < 16; i++) qv[i] = qp[i];
    }

    float m = -1e30f, l = 0.f;
    float acc[64];
#pragma unroll
    for (int c = 0; c < 64; c++) acc[c] = 0.f;

    for (int c0 = 0; c0 < MKV; c0 += CH) {
        __syncthreads();  // previous chunk's compute done before overwriting smem
        // load K/V chunk (gathered) + bias
        if (tid < CH) bias_s[tid] = abias[s * MKV + c0 + tid];
        for (int i = tid; i < CH * 32; i += 224) {
            int j = i >> 5;          // key within chunk
            int inner = i & 31;      // 0..15 -> K float4s, 16..31 -> V float4s
            int tok = gidx[s * MKV + c0 + j];
            if (inner < 16) {
                *(float4*)&Ks[j][inner * 4] =
                    *(const float4*)(kbuf + (size_t)tok * HD + inner * 4);
            } else {
                int c4 = inner - 16;
                *(float4*)&Vs[j][c4 * 4] =
                    *(const float4*)(vbuf + (size_t)tok * HD + c4 * 4);
            }
        }
        __syncthreads();

        if (p < PTOK) {
            float sc[CH];
            float cm = -1e30f;
#pragma unroll
            for (int j = 0; j < CH; j++) {
                const float4* kr = (const float4*)Ks[j];
                float d0 = 0.f, d1 = 0.f, d2 = 0.f, d3 = 0.f;
#pragma unroll
                for (int c4 = 0; c4 < 16; c4++) {
                    float4 kk4 = kr[c4];
                    d0 += qv[c4].x * kk4.x;
                    d1 += qv[c4].y * kk4.y;
                    d2 += qv[c4].z * kk4.z;
                    d3 += qv[c4].w * kk4.w;
                }
                sc[j] = (d0 + d1 + d2 + d3) * 0.125f + bias_s[j];
                cm = fmaxf(cm, sc[j]);
            }
            float mn = fmaxf(m, cm);
            float corr = __expf(m - mn);
            l *= corr;
#pragma unroll
            for (int c = 0; c < 64; c++) acc[c] *= corr;
#pragma unroll
            for (int j = 0; j < CH; j++) {
                float pj = __expf(sc[j] - mn);
                l += pj;
                const float4* vr = (const float4*)Vs[j];
#pragma unroll
                for (int c4 = 0; c4 < 16; c4++) {
                    float4 vv = vr[c4];
                    acc[4 * c4 + 0] += pj * vv.x;
                    acc[4 * c4 + 1] += pj * vv.y;
                    acc[4 * c4 + 2] += pj * vv.z;
                    acc[4 * c4 + 3] += pj * vv.w;
                }
            }
            m = mn;
        }
    }

    if (p < PTOK) {
        float inv = 1.f / l;
        float* op = g_att + (size_t)(s * PTOK + p) * CDIM + h * HD;
#pragma unroll
        for (int c4 = 0; c4 < 16; c4++) {
            float4 o4;
            o4.x = acc[4 * c4 + 0] * inv;
            o4.y = acc[4 * c4 + 1] * inv;
            o4.z = acc[4 * c4 + 2] * inv;
            o4.w = acc[4 * c4 + 3] * inv;
            *(float4*)&op[c4 * 4] = o4;
        }
    }
}

// ---------------------------------------------------------------------------
extern "C" void kernel_launch(void* const* d_in, const int* in_sizes, int n_in,
                              void* d_out, int out_size)
{
    const float* x     = (const float*)d_in[0];
    const float* Wqkv  = (const float*)d_in[1];
    const float* bqkv  = (const float*)d_in[2];
    const float* qg    = (const float*)d_in[3];
    const float* qb    = (const float*)d_in[4];
    const float* kg    = (const float*)d_in[5];
    const float* kb    = (const float*)d_in[6];
    const float* Wproj = (const float*)d_in[7];
    const float* bproj = (const float*)d_in[8];
    const int*   gidx  = (const int*)d_in[9];
    const float* abias = (const float*)d_in[10];
    float* out = (float*)d_out;

    // 1) QKV GEMM with scatter epilogue: 6272 x 3072 x 1024
    {
        dim3 grid(3072 / 128, NTOK / 128);
        sgemm_kernel<0><<<grid, 256>>>(x, Wqkv, bqkv, nullptr, 3072);
    }
    // 2) LayerNorm q/k per (head, token) over D=64
    {
        int nvec = 2 * HEADS * NTOK;                  // warps needed
        int blocks = (nvec * 32 + 255) / 256;
        ln_kernel<<<blocks, 256>>>(qg, qb, kg, kb);
    }
    // 3) Sparse attention per (frame, head)
    {
        dim3 grid(SFR, HEADS);
        attn_kernel<<<grid, 224>>>(gidx, abias);
    }
    // 4) Output projection: 6272 x 1024 x 1024 -> d_out
    {
        dim3 grid(1024 / 128, NTOK / 128);
        sgemm_kernel<1><<<grid, 256>>>(nullptr, Wproj, bproj, out, 1024);
    }
}